// round 1
// baseline (speedup 1.0000x reference)
#include <cuda_runtime.h>
#include <math.h>

// Problem constants
#define B_   2
#define S_   2048
#define HID_ 2560
#define H_   32
#define KV_  8
#define D_   80
#define G_   4
#define BS_  (B_*S_)      // 4096 total rows

// Scratch (device globals: no allocation allowed in kernel_launch)
__device__ float g_Q[(size_t)BS_ * H_ * D_];    // 4096 x 2560
__device__ float g_K[(size_t)BS_ * KV_ * D_];   // 4096 x 640
__device__ float g_V[(size_t)BS_ * KV_ * D_];   // 4096 x 640
__device__ float g_ctx[(size_t)BS_ * H_ * D_];  // 4096 x 2560

// ---------------------------------------------------------------------------
// SGEMM: C[M,N] = A[M,K] @ B[K,N], row-major, fp32.
// 128x128 block, BK=8, 256 threads, 8x8 per-thread microtile.
// All dims are multiples of tile sizes for this problem -> no bounds checks.
// ---------------------------------------------------------------------------
__global__ __launch_bounds__(256) void sgemm128(
    const float* __restrict__ A, const float* __restrict__ Bm,
    float* __restrict__ C, int M, int N, int K)
{
    __shared__ float As[8][128];
    __shared__ float Bs[8][128];

    const int tid  = threadIdx.x;
    const int bm   = blockIdx.y * 128;
    const int bn   = blockIdx.x * 128;
    const int arow = tid >> 1;           // 0..127
    const int acol = (tid & 1) * 4;      // 0 or 4
    const int brow = tid >> 5;           // 0..7
    const int bcol = (tid & 31) * 4;     // 0..124
    const int tx   = tid & 15;
    const int ty   = tid >> 4;

    float acc[8][8];
    #pragma unroll
    for (int i = 0; i < 8; i++)
        #pragma unroll
        for (int j = 0; j < 8; j++) acc[i][j] = 0.f;

    const float* aptr = A + (size_t)(bm + arow) * K + acol;
    const float* bptr = Bm + (size_t)brow * N + bn + bcol;

    for (int k0 = 0; k0 < K; k0 += 8) {
        float4 a4 = *(const float4*)(aptr + k0);
        float4 b4 = *(const float4*)(bptr + (size_t)k0 * N);
        As[acol + 0][arow] = a4.x;
        As[acol + 1][arow] = a4.y;
        As[acol + 2][arow] = a4.z;
        As[acol + 3][arow] = a4.w;
        *(float4*)&Bs[brow][bcol] = b4;
        __syncthreads();

        #pragma unroll
        for (int k = 0; k < 8; k++) {
            float4 a0 = *(const float4*)&As[k][ty * 4];
            float4 a1 = *(const float4*)&As[k][64 + ty * 4];
            float4 b0 = *(const float4*)&Bs[k][tx * 4];
            float4 b1 = *(const float4*)&Bs[k][64 + tx * 4];
            float ra[8] = {a0.x, a0.y, a0.z, a0.w, a1.x, a1.y, a1.z, a1.w};
            float rb[8] = {b0.x, b0.y, b0.z, b0.w, b1.x, b1.y, b1.z, b1.w};
            #pragma unroll
            for (int i = 0; i < 8; i++)
                #pragma unroll
                for (int j = 0; j < 8; j++)
                    acc[i][j] += ra[i] * rb[j];
        }
        __syncthreads();
    }

    #pragma unroll
    for (int i = 0; i < 8; i++) {
        int row = bm + ((i < 4) ? (ty * 4 + i) : (64 + ty * 4 + (i - 4)));
        float* crow = C + (size_t)row * N + bn;
        *(float4*)(crow + tx * 4) =
            make_float4(acc[i][0], acc[i][1], acc[i][2], acc[i][3]);
        *(float4*)(crow + 64 + tx * 4) =
            make_float4(acc[i][4], acc[i][5], acc[i][6], acc[i][7]);
    }
}

// ---------------------------------------------------------------------------
// RoPE (in-place): X layout [BS_, nheads*D]. rotate_half convention:
// out[d]    = x[d]*cos[d]    - x[d+40]*sin[d]       (d < 40)
// out[d+40] = x[d+40]*cos[d+40] + x[d]*sin[d+40]
// One thread per (row, head, d<40) pair.
// ---------------------------------------------------------------------------
__global__ void rope_kernel(float* __restrict__ X,
                            const float* __restrict__ cosf,
                            const float* __restrict__ sinf,
                            int nheads, size_t total)
{
    size_t idx = (size_t)blockIdx.x * blockDim.x + threadIdx.x;
    if (idx >= total) return;
    int d = (int)(idx % 40);
    size_t t = idx / 40;
    int head = (int)(t % nheads);
    size_t row = t / nheads;
    int s = (int)(row % S_);

    float* base = X + row * ((size_t)nheads * D_) + (size_t)head * D_;
    float x1 = base[d];
    float x2 = base[d + 40];
    float c1 = cosf[(size_t)s * D_ + d];
    float s1 = sinf[(size_t)s * D_ + d];
    float c2 = cosf[(size_t)s * D_ + d + 40];
    float s2 = sinf[(size_t)s * D_ + d + 40];
    base[d]      = x1 * c1 - x2 * s1;
    base[d + 40] = x2 * c2 + x1 * s2;
}

// ---------------------------------------------------------------------------
// Flash attention, causal, GQA. One block = (b, h, 64-query tile).
// 256 threads: thread t -> query row qi = t/4, dim-slice g = t%4 (20 dims).
// Online softmax; 4-lane shuffle reductions for row max/sum.
// ---------------------------------------------------------------------------
#define QSTR 84    // smem row stride for Q/K/V tiles (pad 80 -> 84)
#define SSTR 65    // smem row stride for score tile (pad 64 -> 65)

__global__ __launch_bounds__(256) void attn_kernel(
    const float* __restrict__ Q, const float* __restrict__ K,
    const float* __restrict__ V, float* __restrict__ O)
{
    extern __shared__ float sm[];
    float* Qs = sm;                   // 64*QSTR
    float* Ks = Qs + 64 * QSTR;       // 64*QSTR
    float* Vs = Ks + 64 * QSTR;       // 64*QSTR
    float* Ss = Vs + 64 * QSTR;       // 64*SSTR

    const int tid = threadIdx.x;
    const int bh  = blockIdx.y;
    const int b   = bh / H_;
    const int h   = bh % H_;
    const int kvh = h / G_;
    const int q0  = blockIdx.x * 64;
    const float rscale = 0.11180339887498949f;   // 1/sqrt(80)

    // Load + pre-scale Q tile
    for (int i = tid; i < 64 * 80; i += 256) {
        int r = i / 80, d = i % 80;
        Qs[r * QSTR + d] =
            Q[((size_t)(b * S_ + q0 + r)) * (H_ * D_) + h * D_ + d] * rscale;
    }

    const int qi = tid >> 2;   // 0..63
    const int g  = tid & 3;    // 0..3

    float acc[20];
    #pragma unroll
    for (int u = 0; u < 20; u++) acc[u] = 0.f;
    float m = -1e30f, l = 0.f;

    const int kend = q0 + 64;
    for (int k0 = 0; k0 < kend; k0 += 64) {
        __syncthreads();   // prev iteration done with Ks/Vs (+ covers Qs load 1st iter)
        for (int i = tid; i < 64 * 80; i += 256) {
            int r = i / 80, d = i % 80;
            size_t idx = ((size_t)(b * S_ + k0 + r)) * (KV_ * D_) + kvh * D_ + d;
            Ks[r * QSTR + d] = K[idx];
            Vs[r * QSTR + d] = V[idx];
        }
        __syncthreads();

        // Scores: this thread computes row qi, keys ki = g + 4*j, j=0..15
        float sc[16];
        #pragma unroll
        for (int j = 0; j < 16; j++) sc[j] = 0.f;
        const float4* qrow = (const float4*)(Qs + qi * QSTR);
        for (int d4 = 0; d4 < 20; d4++) {
            float4 qv = qrow[d4];
            #pragma unroll
            for (int j = 0; j < 16; j++) {
                float4 kv = *(const float4*)(Ks + (g + 4 * j) * QSTR + 4 * d4);
                sc[j] += qv.x * kv.x + qv.y * kv.y + qv.z * kv.z + qv.w * kv.w;
            }
        }
        // Causal mask
        #pragma unroll
        for (int j = 0; j < 16; j++) {
            int kg = k0 + g + 4 * j;
            if (kg > q0 + qi) sc[j] = -1e30f;
        }
        // Row max across the 4 lanes sharing qi
        float mx = sc[0];
        #pragma unroll
        for (int j = 1; j < 16; j++) mx = fmaxf(mx, sc[j]);
        mx = fmaxf(mx, __shfl_xor_sync(0xffffffffu, mx, 1));
        mx = fmaxf(mx, __shfl_xor_sync(0xffffffffu, mx, 2));
        float mnew = fmaxf(m, mx);
        float corr = __expf(m - mnew);
        float rowsum = 0.f;
        #pragma unroll
        for (int j = 0; j < 16; j++) {
            float p = __expf(sc[j] - mnew);
            sc[j] = p;
            rowsum += p;
        }
        rowsum += __shfl_xor_sync(0xffffffffu, rowsum, 1);
        rowsum += __shfl_xor_sync(0xffffffffu, rowsum, 2);
        m = mnew;
        l = l * corr + rowsum;
        #pragma unroll
        for (int u = 0; u < 20; u++) acc[u] *= corr;
        #pragma unroll
        for (int j = 0; j < 16; j++) Ss[qi * SSTR + g + 4 * j] = sc[j];
        __syncwarp();

        // P @ V  (this thread: row qi, dims [g*20, g*20+20))
        #pragma unroll 8
        for (int ki = 0; ki < 64; ki++) {
            float p = Ss[qi * SSTR + ki];
            const float4* vrow = (const float4*)(Vs + ki * QSTR + g * 20);
            #pragma unroll
            for (int u = 0; u < 5; u++) {
                float4 vv = vrow[u];
                acc[u * 4 + 0] += p * vv.x;
                acc[u * 4 + 1] += p * vv.y;
                acc[u * 4 + 2] += p * vv.z;
                acc[u * 4 + 3] += p * vv.w;
            }
        }
        __syncwarp();  // Ss reads done before next iteration overwrites
    }

    float inv = 1.f / l;
    float* orow = O + ((size_t)(b * S_ + q0 + qi)) * (H_ * D_) + h * D_ + g * 20;
    #pragma unroll
    for (int u = 0; u < 5; u++) {
        *(float4*)(orow + 4 * u) = make_float4(acc[u * 4 + 0] * inv,
                                               acc[u * 4 + 1] * inv,
                                               acc[u * 4 + 2] * inv,
                                               acc[u * 4 + 3] * inv);
    }
}

// ---------------------------------------------------------------------------
// Launch
// ---------------------------------------------------------------------------
extern "C" void kernel_launch(void* const* d_in, const int* in_sizes, int n_in,
                              void* d_out, int out_size)
{
    const float* hs   = (const float*)d_in[0];   // [2,2048,2560]
    const float* cosf = (const float*)d_in[1];   // [2048,80]
    const float* sinf = (const float*)d_in[2];   // [2048,80]
    const float* Wq   = (const float*)d_in[3];   // [2560,2560]
    const float* Wk   = (const float*)d_in[4];   // [2560,640]
    const float* Wv   = (const float*)d_in[5];   // [2560,640]
    const float* Wo   = (const float*)d_in[6];   // [2560,2560]
    float* out = (float*)d_out;

    float *Qp, *Kp, *Vp, *Cp;
    cudaGetSymbolAddress((void**)&Qp, g_Q);
    cudaGetSymbolAddress((void**)&Kp, g_K);
    cudaGetSymbolAddress((void**)&Vp, g_V);
    cudaGetSymbolAddress((void**)&Cp, g_ctx);

    // QKV projections
    {
        dim3 gq(HID_ / 128, BS_ / 128);          // (20, 32)
        sgemm128<<<gq, 256>>>(hs, Wq, Qp, BS_, H_ * D_, HID_);
        dim3 gkv((KV_ * D_) / 128, BS_ / 128);   // (5, 32)
        sgemm128<<<gkv, 256>>>(hs, Wk, Kp, BS_, KV_ * D_, HID_);
        sgemm128<<<gkv, 256>>>(hs, Wv, Vp, BS_, KV_ * D_, HID_);
    }

    // RoPE on Q and K
    {
        size_t tq = (size_t)BS_ * H_ * 40;
        size_t tk = (size_t)BS_ * KV_ * 40;
        rope_kernel<<<(unsigned)((tq + 255) / 256), 256>>>(Qp, cosf, sinf, H_, tq);
        rope_kernel<<<(unsigned)((tk + 255) / 256), 256>>>(Kp, cosf, sinf, KV_, tk);
    }

    // Attention
    {
        const int smem = (3 * 64 * QSTR + 64 * SSTR) * (int)sizeof(float); // 81152
        cudaFuncSetAttribute(attn_kernel,
                             cudaFuncAttributeMaxDynamicSharedMemorySize, smem);
        dim3 ga(S_ / 64, B_ * H_);               // (32, 64)
        attn_kernel<<<ga, 256, smem>>>(Qp, Kp, Vp, Cp);
    }

    // Output projection
    {
        dim3 go(HID_ / 128, BS_ / 128);          // (20, 32)
        sgemm128<<<go, 256>>>(Cp, Wo, out, BS_, HID_, HID_);
    }
}

// round 2
// speedup vs baseline: 1.6408x; 1.6408x over previous
#include <cuda_runtime.h>
#include <math.h>

// Problem constants
#define B_   2
#define S_   2048
#define HID_ 2560
#define H_   32
#define KV_  8
#define D_   80
#define G_   4
#define BS_  (B_*S_)      // 4096 total rows

// Scratch (device globals: no allocation allowed in kernel_launch)
__device__ float g_Q[(size_t)BS_ * H_ * D_];    // 4096 x 2560
__device__ float g_K[(size_t)BS_ * KV_ * D_];   // 4096 x 640
__device__ float g_V[(size_t)BS_ * KV_ * D_];   // 4096 x 640
__device__ float g_ctx[(size_t)BS_ * H_ * D_];  // 4096 x 2560 (tf32-rounded)
// TF32-rounded copies of inputs
__device__ float g_hs_r[(size_t)BS_ * HID_];
__device__ float g_Wq_r[(size_t)HID_ * H_ * D_];
__device__ float g_Wk_r[(size_t)HID_ * KV_ * D_];
__device__ float g_Wv_r[(size_t)HID_ * KV_ * D_];
__device__ float g_Wo_r[(size_t)H_ * D_ * HID_];

// ---------------------------------------------------------------------------
// Helpers
// ---------------------------------------------------------------------------
__device__ __forceinline__ unsigned smem_u32(const void* p) {
    return (unsigned)__cvta_generic_to_shared(p);
}
__device__ __forceinline__ void cp_async16(unsigned dst, const void* src) {
    asm volatile("cp.async.cg.shared.global [%0], [%1], 16;\n"
                 :: "r"(dst), "l"(src));
}
#define CP_COMMIT() asm volatile("cp.async.commit_group;\n" ::: "memory")
#define CP_WAIT0()  asm volatile("cp.async.wait_group 0;\n" ::: "memory")

__device__ __forceinline__ float tf32_rna(float v) {
    unsigned u;
    asm("cvt.rna.tf32.f32 %0, %1;" : "=r"(u) : "f"(v));
    return __uint_as_float(u);
}

__device__ __forceinline__ void mma_tf32(float* c, const unsigned* a, const unsigned* b) {
    asm volatile(
        "mma.sync.aligned.m16n8k8.row.col.f32.tf32.tf32.f32 "
        "{%0,%1,%2,%3}, {%4,%5,%6,%7}, {%8,%9}, {%0,%1,%2,%3};\n"
        : "+f"(c[0]), "+f"(c[1]), "+f"(c[2]), "+f"(c[3])
        : "r"(a[0]), "r"(a[1]), "r"(a[2]), "r"(a[3]), "r"(b[0]), "r"(b[1]));
}

// ---------------------------------------------------------------------------
// TF32 RNA rounding pre-pass (vectorized)
// ---------------------------------------------------------------------------
__global__ void round_tf32(const float4* __restrict__ in,
                           float4* __restrict__ out, int n4)
{
    int i = blockIdx.x * blockDim.x + threadIdx.x;
    if (i < n4) {
        float4 v = in[i];
        v.x = tf32_rna(v.x); v.y = tf32_rna(v.y);
        v.z = tf32_rna(v.z); v.w = tf32_rna(v.w);
        out[i] = v;
    }
}

// ---------------------------------------------------------------------------
// TF32 tensor-core GEMM core: C[128x128 tile] = A[M,K] @ B[K,N]
// BK=16, 256 threads, 8 warps (2x4), warp tile 64x32, double-buffered cp.async.
// Smem strides 20 (A) / 136 (B) -> conflict-free fragment LDS.
// ---------------------------------------------------------------------------
#define ASTR 20
#define BSTR 136

__device__ __forceinline__ void gemm_core(
    const float* __restrict__ A, const float* __restrict__ Bm,
    float* __restrict__ C, int N, int K, int bm, int bn)
{
    __shared__ float As[2][128 * ASTR];
    __shared__ float Bs[2][16 * BSTR];

    const int tid  = threadIdx.x;
    const int lane = tid & 31;
    const int w    = tid >> 5;
    const int wm   = (w >> 2) * 64;   // 0 or 64
    const int wn   = (w & 3) * 32;    // 0..96
    const int lr   = lane >> 2;       // 0..7
    const int lc   = lane & 3;        // 0..3

    // gmem->smem load indices
    const int a_row = tid >> 2;         // 0..63 (+64)
    const int a_col = (tid & 3) * 4;    // 0,4,8,12
    const int b_row = tid >> 5;         // 0..7 (+8)
    const int b_col = (tid & 31) * 4;   // 0..124

    float acc[4][4][4];
    #pragma unroll
    for (int mi = 0; mi < 4; mi++)
        #pragma unroll
        for (int nj = 0; nj < 4; nj++)
            #pragma unroll
            for (int u = 0; u < 4; u++) acc[mi][nj][u] = 0.f;

    const int T = K / 16;

    // tile loader
    auto load_tile = [&](int kt, int buf) {
        const float* ag = A + (size_t)(bm + a_row) * K + kt * 16 + a_col;
        unsigned as0 = smem_u32(&As[buf][a_row * ASTR + a_col]);
        cp_async16(as0, ag);
        cp_async16(as0 + 64 * ASTR * 4, ag + (size_t)64 * K);
        const float* bg = Bm + (size_t)(kt * 16 + b_row) * N + bn + b_col;
        unsigned bs0 = smem_u32(&Bs[buf][b_row * BSTR + b_col]);
        cp_async16(bs0, bg);
        cp_async16(bs0 + 8 * BSTR * 4, bg + (size_t)8 * N);
    };

    load_tile(0, 0);
    CP_COMMIT();

    for (int kt = 0; kt < T; kt++) {
        const int buf = kt & 1;
        CP_WAIT0();
        __syncthreads();
        if (kt + 1 < T) {
            load_tile(kt + 1, buf ^ 1);
            CP_COMMIT();
        }
        #pragma unroll
        for (int ks = 0; ks < 2; ks++) {
            const int kc = lc + ks * 8;
            unsigned af[4][4], bf[4][2];
            #pragma unroll
            for (int mi = 0; mi < 4; mi++) {
                int r = wm + mi * 16 + lr;
                af[mi][0] = __float_as_uint(As[buf][r * ASTR + kc]);
                af[mi][1] = __float_as_uint(As[buf][(r + 8) * ASTR + kc]);
                af[mi][2] = __float_as_uint(As[buf][r * ASTR + kc + 4]);
                af[mi][3] = __float_as_uint(As[buf][(r + 8) * ASTR + kc + 4]);
            }
            #pragma unroll
            for (int nj = 0; nj < 4; nj++) {
                int cn = wn + nj * 8 + lr;
                bf[nj][0] = __float_as_uint(Bs[buf][kc * BSTR + cn]);
                bf[nj][1] = __float_as_uint(Bs[buf][(kc + 4) * BSTR + cn]);
            }
            #pragma unroll
            for (int mi = 0; mi < 4; mi++)
                #pragma unroll
                for (int nj = 0; nj < 4; nj++)
                    mma_tf32(acc[mi][nj], af[mi], bf[nj]);
        }
    }

    // epilogue
    #pragma unroll
    for (int mi = 0; mi < 4; mi++) {
        int r0 = bm + wm + mi * 16 + lr;
        #pragma unroll
        for (int nj = 0; nj < 4; nj++) {
            int cn = bn + wn + nj * 8 + 2 * lc;
            *(float2*)&C[(size_t)r0 * N + cn] =
                make_float2(acc[mi][nj][0], acc[mi][nj][1]);
            *(float2*)&C[(size_t)(r0 + 8) * N + cn] =
                make_float2(acc[mi][nj][2], acc[mi][nj][3]);
        }
    }
}

// Generic GEMM (used for Wo)
__global__ __launch_bounds__(256) void gemm_tf32(
    const float* __restrict__ A, const float* __restrict__ Bm,
    float* __restrict__ C, int N, int K)
{
    gemm_core(A, Bm, C, N, K, blockIdx.y * 128, blockIdx.x * 128);
}

// Fused Q/K/V projection: grid.x = 30 (20 Q tiles, 5 K, 5 V)
__global__ __launch_bounds__(256) void gemm_qkv(
    const float* __restrict__ A,
    const float* __restrict__ Wq, float* __restrict__ Qo,
    const float* __restrict__ Wk, float* __restrict__ Ko,
    const float* __restrict__ Wv, float* __restrict__ Vo)
{
    const int bx = blockIdx.x;
    const int bm = blockIdx.y * 128;
    if (bx < 20)       gemm_core(A, Wq, Qo, HID_,      HID_, bm, bx * 128);
    else if (bx < 25)  gemm_core(A, Wk, Ko, KV_ * D_,  HID_, bm, (bx - 20) * 128);
    else               gemm_core(A, Wv, Vo, KV_ * D_,  HID_, bm, (bx - 25) * 128);
}

// ---------------------------------------------------------------------------
// RoPE (in-place)
// ---------------------------------------------------------------------------
__global__ void rope_kernel(float* __restrict__ X,
                            const float* __restrict__ cosf,
                            const float* __restrict__ sinf,
                            int nheads, size_t total)
{
    size_t idx = (size_t)blockIdx.x * blockDim.x + threadIdx.x;
    if (idx >= total) return;
    int d = (int)(idx % 40);
    size_t t = idx / 40;
    int head = (int)(t % nheads);
    size_t row = t / nheads;
    int s = (int)(row % S_);

    float* base = X + row * ((size_t)nheads * D_) + (size_t)head * D_;
    float x1 = base[d];
    float x2 = base[d + 40];
    float c1 = cosf[(size_t)s * D_ + d];
    float s1 = sinf[(size_t)s * D_ + d];
    float c2 = cosf[(size_t)s * D_ + d + 40];
    float s2 = sinf[(size_t)s * D_ + d + 40];
    base[d]      = x1 * c1 - x2 * s1;
    base[d + 40] = x2 * c2 + x1 * s2;
}

// ---------------------------------------------------------------------------
// Flash attention, causal, GQA (fp32 SIMT; ctx output tf32-rounded)
// ---------------------------------------------------------------------------
#define QSTR 84
#define SSTR 65

__global__ __launch_bounds__(256) void attn_kernel(
    const float* __restrict__ Q, const float* __restrict__ K,
    const float* __restrict__ V, float* __restrict__ O)
{
    extern __shared__ float sm[];
    float* Qs = sm;
    float* Ks = Qs + 64 * QSTR;
    float* Vs = Ks + 64 * QSTR;
    float* Ss = Vs + 64 * QSTR;

    const int tid = threadIdx.x;
    const int bh  = blockIdx.y;
    const int b   = bh / H_;
    const int h   = bh % H_;
    const int kvh = h / G_;
    const int q0  = blockIdx.x * 64;
    const float rscale = 0.11180339887498949f;   // 1/sqrt(80)

    for (int i = tid; i < 64 * 80; i += 256) {
        int r = i / 80, d = i % 80;
        Qs[r * QSTR + d] =
            Q[((size_t)(b * S_ + q0 + r)) * (H_ * D_) + h * D_ + d] * rscale;
    }

    const int qi = tid >> 2;
    const int g  = tid & 3;

    float acc[20];
    #pragma unroll
    for (int u = 0; u < 20; u++) acc[u] = 0.f;
    float m = -1e30f, l = 0.f;

    const int kend = q0 + 64;
    for (int k0 = 0; k0 < kend; k0 += 64) {
        __syncthreads();
        for (int i = tid; i < 64 * 80; i += 256) {
            int r = i / 80, d = i % 80;
            size_t idx = ((size_t)(b * S_ + k0 + r)) * (KV_ * D_) + kvh * D_ + d;
            Ks[r * QSTR + d] = K[idx];
            Vs[r * QSTR + d] = V[idx];
        }
        __syncthreads();

        float sc[16];
        #pragma unroll
        for (int j = 0; j < 16; j++) sc[j] = 0.f;
        const float4* qrow = (const float4*)(Qs + qi * QSTR);
        for (int d4 = 0; d4 < 20; d4++) {
            float4 qv = qrow[d4];
            #pragma unroll
            for (int j = 0; j < 16; j++) {
                float4 kv = *(const float4*)(Ks + (g + 4 * j) * QSTR + 4 * d4);
                sc[j] += qv.x * kv.x + qv.y * kv.y + qv.z * kv.z + qv.w * kv.w;
            }
        }
        #pragma unroll
        for (int j = 0; j < 16; j++) {
            int kg = k0 + g + 4 * j;
            if (kg > q0 + qi) sc[j] = -1e30f;
        }
        float mx = sc[0];
        #pragma unroll
        for (int j = 1; j < 16; j++) mx = fmaxf(mx, sc[j]);
        mx = fmaxf(mx, __shfl_xor_sync(0xffffffffu, mx, 1));
        mx = fmaxf(mx, __shfl_xor_sync(0xffffffffu, mx, 2));
        float mnew = fmaxf(m, mx);
        float corr = __expf(m - mnew);
        float rowsum = 0.f;
        #pragma unroll
        for (int j = 0; j < 16; j++) {
            float p = __expf(sc[j] - mnew);
            sc[j] = p;
            rowsum += p;
        }
        rowsum += __shfl_xor_sync(0xffffffffu, rowsum, 1);
        rowsum += __shfl_xor_sync(0xffffffffu, rowsum, 2);
        m = mnew;
        l = l * corr + rowsum;
        #pragma unroll
        for (int u = 0; u < 20; u++) acc[u] *= corr;
        #pragma unroll
        for (int j = 0; j < 16; j++) Ss[qi * SSTR + g + 4 * j] = sc[j];
        __syncwarp();

        #pragma unroll 8
        for (int ki = 0; ki < 64; ki++) {
            float p = Ss[qi * SSTR + ki];
            const float4* vrow = (const float4*)(Vs + ki * QSTR + g * 20);
            #pragma unroll
            for (int u = 0; u < 5; u++) {
                float4 vv = vrow[u];
                acc[u * 4 + 0] += p * vv.x;
                acc[u * 4 + 1] += p * vv.y;
                acc[u * 4 + 2] += p * vv.z;
                acc[u * 4 + 3] += p * vv.w;
            }
        }
        __syncwarp();
    }

    float inv = 1.f / l;
    float* orow = O + ((size_t)(b * S_ + q0 + qi)) * (H_ * D_) + h * D_ + g * 20;
    #pragma unroll
    for (int u = 0; u < 5; u++) {
        *(float4*)(orow + 4 * u) =
            make_float4(tf32_rna(acc[u * 4 + 0] * inv),
                        tf32_rna(acc[u * 4 + 1] * inv),
                        tf32_rna(acc[u * 4 + 2] * inv),
                        tf32_rna(acc[u * 4 + 3] * inv));
    }
}

// ---------------------------------------------------------------------------
// Launch
// ---------------------------------------------------------------------------
extern "C" void kernel_launch(void* const* d_in, const int* in_sizes, int n_in,
                              void* d_out, int out_size)
{
    const float* hs   = (const float*)d_in[0];
    const float* cosf = (const float*)d_in[1];
    const float* sinf = (const float*)d_in[2];
    const float* Wq   = (const float*)d_in[3];
    const float* Wk   = (const float*)d_in[4];
    const float* Wv   = (const float*)d_in[5];
    const float* Wo   = (const float*)d_in[6];
    float* out = (float*)d_out;

    float *Qp, *Kp, *Vp, *Cp, *HSr, *Wqr, *Wkr, *Wvr, *Wor;
    cudaGetSymbolAddress((void**)&Qp,  g_Q);
    cudaGetSymbolAddress((void**)&Kp,  g_K);
    cudaGetSymbolAddress((void**)&Vp,  g_V);
    cudaGetSymbolAddress((void**)&Cp,  g_ctx);
    cudaGetSymbolAddress((void**)&HSr, g_hs_r);
    cudaGetSymbolAddress((void**)&Wqr, g_Wq_r);
    cudaGetSymbolAddress((void**)&Wkr, g_Wk_r);
    cudaGetSymbolAddress((void**)&Wvr, g_Wv_r);
    cudaGetSymbolAddress((void**)&Wor, g_Wo_r);

    // TF32 RNA pre-rounding
    {
        auto rnd = [](const float* src, float* dst, size_t n) {
            int n4 = (int)(n / 4);
            round_tf32<<<(n4 + 255) / 256, 256>>>(
                (const float4*)src, (float4*)dst, n4);
        };
        rnd(hs, HSr, (size_t)BS_ * HID_);
        rnd(Wq, Wqr, (size_t)HID_ * H_ * D_);
        rnd(Wk, Wkr, (size_t)HID_ * KV_ * D_);
        rnd(Wv, Wvr, (size_t)HID_ * KV_ * D_);
        rnd(Wo, Wor, (size_t)H_ * D_ * HID_);
    }

    // Fused QKV projection (tensor cores)
    {
        dim3 g(30, BS_ / 128);
        gemm_qkv<<<g, 256>>>(HSr, Wqr, Qp, Wkr, Kp, Wvr, Vp);
    }

    // RoPE on Q and K
    {
        size_t tq = (size_t)BS_ * H_ * 40;
        size_t tk = (size_t)BS_ * KV_ * 40;
        rope_kernel<<<(unsigned)((tq + 255) / 256), 256>>>(Qp, cosf, sinf, H_, tq);
        rope_kernel<<<(unsigned)((tk + 255) / 256), 256>>>(Kp, cosf, sinf, KV_, tk);
    }

    // Attention
    {
        const int smem = (3 * 64 * QSTR + 64 * SSTR) * (int)sizeof(float);
        cudaFuncSetAttribute(attn_kernel,
                             cudaFuncAttributeMaxDynamicSharedMemorySize, smem);
        dim3 ga(S_ / 64, B_ * H_);
        attn_kernel<<<ga, 256, smem>>>(Qp, Kp, Vp, Cp);
    }

    // Output projection (tensor cores)
    {
        dim3 go(HID_ / 128, BS_ / 128);
        gemm_tf32<<<go, 256>>>(Cp, Wor, out, HID_, HID_);
    }
}

// round 3
// speedup vs baseline: 2.7250x; 1.6608x over previous
#include <cuda_runtime.h>
#include <math.h>

// Problem constants
#define B_   2
#define S_   2048
#define HID_ 2560
#define H_   32
#define KV_  8
#define D_   80
#define G_   4
#define BS_  (B_*S_)      // 4096 total rows

// Scratch (device globals)
__device__ float g_Q[(size_t)BS_ * H_ * D_];
__device__ float g_K[(size_t)BS_ * KV_ * D_];
__device__ float g_V[(size_t)BS_ * KV_ * D_];
__device__ float g_ctx[(size_t)BS_ * H_ * D_];
__device__ float g_hs_r[(size_t)BS_ * HID_];
__device__ float g_Wq_r[(size_t)HID_ * H_ * D_];
__device__ float g_Wk_r[(size_t)HID_ * KV_ * D_];
__device__ float g_Wv_r[(size_t)HID_ * KV_ * D_];
__device__ float g_Wo_r[(size_t)H_ * D_ * HID_];

// ---------------------------------------------------------------------------
// Helpers
// ---------------------------------------------------------------------------
__device__ __forceinline__ unsigned smem_u32(const void* p) {
    return (unsigned)__cvta_generic_to_shared(p);
}
__device__ __forceinline__ void cp_async16(unsigned dst, const void* src) {
    asm volatile("cp.async.cg.shared.global [%0], [%1], 16;\n"
                 :: "r"(dst), "l"(src));
}
#define CP_COMMIT() asm volatile("cp.async.commit_group;\n" ::: "memory")
#define CP_WAIT0()  asm volatile("cp.async.wait_group 0;\n" ::: "memory")

__device__ __forceinline__ float tf32_rna(float v) {
    unsigned u;
    asm("cvt.rna.tf32.f32 %0, %1;" : "=r"(u) : "f"(v));
    return __uint_as_float(u);
}

__device__ __forceinline__ void mma_tf32(float* c, const unsigned* a, const unsigned* b) {
    asm volatile(
        "mma.sync.aligned.m16n8k8.row.col.f32.tf32.tf32.f32 "
        "{%0,%1,%2,%3}, {%4,%5,%6,%7}, {%8,%9}, {%0,%1,%2,%3};\n"
        : "+f"(c[0]), "+f"(c[1]), "+f"(c[2]), "+f"(c[3])
        : "r"(a[0]), "r"(a[1]), "r"(a[2]), "r"(a[3]), "r"(b[0]), "r"(b[1]));
}

// ---------------------------------------------------------------------------
// TF32 RNA rounding pre-pass
// ---------------------------------------------------------------------------
__global__ void round_tf32(const float4* __restrict__ in,
                           float4* __restrict__ out, int n4)
{
    int i = blockIdx.x * blockDim.x + threadIdx.x;
    if (i < n4) {
        float4 v = in[i];
        v.x = tf32_rna(v.x); v.y = tf32_rna(v.y);
        v.z = tf32_rna(v.z); v.w = tf32_rna(v.w);
        out[i] = v;
    }
}

// ---------------------------------------------------------------------------
// TF32 tensor-core GEMM (unchanged from round 2)
// ---------------------------------------------------------------------------
#define ASTR 20
#define BSTR 136

__device__ __forceinline__ void gemm_core(
    const float* __restrict__ A, const float* __restrict__ Bm,
    float* __restrict__ C, int N, int K, int bm, int bn)
{
    __shared__ float As[2][128 * ASTR];
    __shared__ float Bs[2][16 * BSTR];

    const int tid  = threadIdx.x;
    const int lane = tid & 31;
    const int w    = tid >> 5;
    const int wm   = (w >> 2) * 64;
    const int wn   = (w & 3) * 32;
    const int lr   = lane >> 2;
    const int lc   = lane & 3;

    const int a_row = tid >> 2;
    const int a_col = (tid & 3) * 4;
    const int b_row = tid >> 5;
    const int b_col = (tid & 31) * 4;

    float acc[4][4][4];
    #pragma unroll
    for (int mi = 0; mi < 4; mi++)
        #pragma unroll
        for (int nj = 0; nj < 4; nj++)
            #pragma unroll
            for (int u = 0; u < 4; u++) acc[mi][nj][u] = 0.f;

    const int T = K / 16;

    auto load_tile = [&](int kt, int buf) {
        const float* ag = A + (size_t)(bm + a_row) * K + kt * 16 + a_col;
        unsigned as0 = smem_u32(&As[buf][a_row * ASTR + a_col]);
        cp_async16(as0, ag);
        cp_async16(as0 + 64 * ASTR * 4, ag + (size_t)64 * K);
        const float* bg = Bm + (size_t)(kt * 16 + b_row) * N + bn + b_col;
        unsigned bs0 = smem_u32(&Bs[buf][b_row * BSTR + b_col]);
        cp_async16(bs0, bg);
        cp_async16(bs0 + 8 * BSTR * 4, bg + (size_t)8 * N);
    };

    load_tile(0, 0);
    CP_COMMIT();

    for (int kt = 0; kt < T; kt++) {
        const int buf = kt & 1;
        CP_WAIT0();
        __syncthreads();
        if (kt + 1 < T) {
            load_tile(kt + 1, buf ^ 1);
            CP_COMMIT();
        }
        #pragma unroll
        for (int ks = 0; ks < 2; ks++) {
            const int kc = lc + ks * 8;
            unsigned af[4][4], bf[4][2];
            #pragma unroll
            for (int mi = 0; mi < 4; mi++) {
                int r = wm + mi * 16 + lr;
                af[mi][0] = __float_as_uint(As[buf][r * ASTR + kc]);
                af[mi][1] = __float_as_uint(As[buf][(r + 8) * ASTR + kc]);
                af[mi][2] = __float_as_uint(As[buf][r * ASTR + kc + 4]);
                af[mi][3] = __float_as_uint(As[buf][(r + 8) * ASTR + kc + 4]);
            }
            #pragma unroll
            for (int nj = 0; nj < 4; nj++) {
                int cn = wn + nj * 8 + lr;
                bf[nj][0] = __float_as_uint(Bs[buf][kc * BSTR + cn]);
                bf[nj][1] = __float_as_uint(Bs[buf][(kc + 4) * BSTR + cn]);
            }
            #pragma unroll
            for (int mi = 0; mi < 4; mi++)
                #pragma unroll
                for (int nj = 0; nj < 4; nj++)
                    mma_tf32(acc[mi][nj], af[mi], bf[nj]);
        }
    }

    #pragma unroll
    for (int mi = 0; mi < 4; mi++) {
        int r0 = bm + wm + mi * 16 + lr;
        #pragma unroll
        for (int nj = 0; nj < 4; nj++) {
            int cn = bn + wn + nj * 8 + 2 * lc;
            *(float2*)&C[(size_t)r0 * N + cn] =
                make_float2(acc[mi][nj][0], acc[mi][nj][1]);
            *(float2*)&C[(size_t)(r0 + 8) * N + cn] =
                make_float2(acc[mi][nj][2], acc[mi][nj][3]);
        }
    }
}

__global__ __launch_bounds__(256) void gemm_tf32(
    const float* __restrict__ A, const float* __restrict__ Bm,
    float* __restrict__ C, int N, int K)
{
    gemm_core(A, Bm, C, N, K, blockIdx.y * 128, blockIdx.x * 128);
}

__global__ __launch_bounds__(256) void gemm_qkv(
    const float* __restrict__ A,
    const float* __restrict__ Wq, float* __restrict__ Qo,
    const float* __restrict__ Wk, float* __restrict__ Ko,
    const float* __restrict__ Wv, float* __restrict__ Vo)
{
    const int bx = blockIdx.x;
    const int bm = blockIdx.y * 128;
    if (bx < 20)       gemm_core(A, Wq, Qo, HID_,      HID_, bm, bx * 128);
    else if (bx < 25)  gemm_core(A, Wk, Ko, KV_ * D_,  HID_, bm, (bx - 20) * 128);
    else               gemm_core(A, Wv, Vo, KV_ * D_,  HID_, bm, (bx - 25) * 128);
}

// ---------------------------------------------------------------------------
// RoPE (in-place)
// ---------------------------------------------------------------------------
__global__ void rope_kernel(float* __restrict__ X,
                            const float* __restrict__ cosf,
                            const float* __restrict__ sinf,
                            int nheads, size_t total)
{
    size_t idx = (size_t)blockIdx.x * blockDim.x + threadIdx.x;
    if (idx >= total) return;
    int d = (int)(idx % 40);
    size_t t = idx / 40;
    int head = (int)(t % nheads);
    size_t row = t / nheads;
    int s = (int)(row % S_);

    float* base = X + row * ((size_t)nheads * D_) + (size_t)head * D_;
    float x1 = base[d];
    float x2 = base[d + 40];
    float c1 = cosf[(size_t)s * D_ + d];
    float s1 = sinf[(size_t)s * D_ + d];
    float c2 = cosf[(size_t)s * D_ + d + 40];
    float s2 = sinf[(size_t)s * D_ + d + 40];
    base[d]      = x1 * c1 - x2 * s1;
    base[d + 40] = x2 * c2 + x1 * s2;
}

// ---------------------------------------------------------------------------
// Flash attention via tf32 mma with 3x split-compensation (fp32-level accuracy)
// BQ=BK=64, 8 warps = 4(m)x2(n). Smem strides: 84 (Q/K), 88 (V), 68 (P).
// ---------------------------------------------------------------------------
#define AQ 84
#define AV 88
#define AP 68

__global__ __launch_bounds__(256) void attn_mma(
    const float* __restrict__ Q, const float* __restrict__ K,
    const float* __restrict__ V, float* __restrict__ O)
{
    extern __shared__ float sm[];
    float* Qhi = sm;                 // 64*84
    float* Qlo = Qhi + 64 * AQ;
    float* Khi = Qlo + 64 * AQ;
    float* Klo = Khi + 64 * AQ;
    float* Vhi = Klo + 64 * AQ;      // 64*88
    float* Vlo = Vhi + 64 * AV;
    float* Ph  = Vlo + 64 * AV;      // 64*68 (raw scores, then P hi)
    float* Pl  = Ph  + 64 * AP;      // P lo
    float* cr  = Pl  + 64 * AP;      // 64: corr factor / final 1/l

    const int tid  = threadIdx.x;
    const int lane = tid & 31;
    const int w    = tid >> 5;
    const int lr   = lane >> 2;
    const int lc   = lane & 3;
    const int wm   = (w >> 1) * 16;   // 0,16,32,48
    const int wnq  = (w & 1) * 32;    // QK n-offset
    const int wnp  = (w & 1) * 40;    // PV n-offset

    const int bh  = blockIdx.y;
    const int b   = bh / H_;
    const int h   = bh % H_;
    const int kvh = h / G_;
    const int q0  = blockIdx.x * 64;
    const float rscale = 0.11180339887498949f;  // 1/sqrt(80)

    // Load + scale + split Q tile
    for (int i = tid; i < 64 * 20; i += 256) {
        int r = i / 20, c4 = (i % 20) * 4;
        float4 v = *(const float4*)(Q + ((size_t)(b * S_ + q0 + r)) * (H_ * D_)
                                      + h * D_ + c4);
        v.x *= rscale; v.y *= rscale; v.z *= rscale; v.w *= rscale;
        float4 hi, lo;
        hi.x = tf32_rna(v.x); lo.x = tf32_rna(v.x - hi.x);
        hi.y = tf32_rna(v.y); lo.y = tf32_rna(v.y - hi.y);
        hi.z = tf32_rna(v.z); lo.z = tf32_rna(v.z - hi.z);
        hi.w = tf32_rna(v.w); lo.w = tf32_rna(v.w - hi.w);
        *(float4*)(Qhi + r * AQ + c4) = hi;
        *(float4*)(Qlo + r * AQ + c4) = lo;
    }

    const int myrow = tid >> 2;     // softmax row ownership
    const int myg   = tid & 3;
    float m = -1e30f, l = 0.f;

    float co[5][4];
    #pragma unroll
    for (int nj = 0; nj < 5; nj++)
        #pragma unroll
        for (int u = 0; u < 4; u++) co[nj][u] = 0.f;

    for (int k0 = 0; k0 <= q0; k0 += 64) {
        __syncthreads();   // prev iter done with Khi..Vlo, Ph/Pl
        // Load + split K,V tiles
        for (int i = tid; i < 64 * 20; i += 256) {
            int r = i / 20, c4 = (i % 20) * 4;
            size_t base = ((size_t)(b * S_ + k0 + r)) * (KV_ * D_) + kvh * D_ + c4;
            float4 kv = *(const float4*)(K + base);
            float4 vv = *(const float4*)(V + base);
            float4 hi, lo;
            hi.x = tf32_rna(kv.x); lo.x = tf32_rna(kv.x - hi.x);
            hi.y = tf32_rna(kv.y); lo.y = tf32_rna(kv.y - hi.y);
            hi.z = tf32_rna(kv.z); lo.z = tf32_rna(kv.z - hi.z);
            hi.w = tf32_rna(kv.w); lo.w = tf32_rna(kv.w - hi.w);
            *(float4*)(Khi + r * AQ + c4) = hi;
            *(float4*)(Klo + r * AQ + c4) = lo;
            hi.x = tf32_rna(vv.x); lo.x = tf32_rna(vv.x - hi.x);
            hi.y = tf32_rna(vv.y); lo.y = tf32_rna(vv.y - hi.y);
            hi.z = tf32_rna(vv.z); lo.z = tf32_rna(vv.z - hi.z);
            hi.w = tf32_rna(vv.w); lo.w = tf32_rna(vv.w - hi.w);
            *(float4*)(Vhi + r * AV + c4) = hi;
            *(float4*)(Vlo + r * AV + c4) = lo;
        }
        __syncthreads();

        // QK^T: 3 compensated passes
        float cq[4][4];
        #pragma unroll
        for (int nj = 0; nj < 4; nj++)
            #pragma unroll
            for (int u = 0; u < 4; u++) cq[nj][u] = 0.f;

        #pragma unroll
        for (int pass = 0; pass < 3; pass++) {
            const float* Av = (pass == 1) ? Qlo : Qhi;
            const float* Bv = (pass == 2) ? Klo : Khi;
            #pragma unroll
            for (int ks = 0; ks < 10; ks++) {
                int kc = ks * 8 + lc;
                unsigned a[4];
                a[0] = __float_as_uint(Av[(wm + lr) * AQ + kc]);
                a[1] = __float_as_uint(Av[(wm + lr + 8) * AQ + kc]);
                a[2] = __float_as_uint(Av[(wm + lr) * AQ + kc + 4]);
                a[3] = __float_as_uint(Av[(wm + lr + 8) * AQ + kc + 4]);
                #pragma unroll
                for (int nj = 0; nj < 4; nj++) {
                    int cn = wnq + nj * 8 + lr;
                    unsigned bb[2];
                    bb[0] = __float_as_uint(Bv[cn * AQ + kc]);
                    bb[1] = __float_as_uint(Bv[cn * AQ + kc + 4]);
                    mma_tf32(cq[nj], a, bb);
                }
            }
        }

        // Mask + store raw scores
        #pragma unroll
        for (int nj = 0; nj < 4; nj++) {
            int col = wnq + nj * 8 + 2 * lc;
            int r0 = wm + lr, r1 = wm + lr + 8;
            Ph[r0 * AP + col]     = (k0 + col     <= q0 + r0) ? cq[nj][0] : -1e30f;
            Ph[r0 * AP + col + 1] = (k0 + col + 1 <= q0 + r0) ? cq[nj][1] : -1e30f;
            Ph[r1 * AP + col]     = (k0 + col     <= q0 + r1) ? cq[nj][2] : -1e30f;
            Ph[r1 * AP + col + 1] = (k0 + col + 1 <= q0 + r1) ? cq[nj][3] : -1e30f;
        }
        __syncthreads();

        // Online softmax: thread (myrow, myg) handles 16 cols
        float s[16];
        #pragma unroll
        for (int j4 = 0; j4 < 4; j4++) {
            float4 v4 = *(const float4*)(Ph + myrow * AP + myg * 16 + j4 * 4);
            s[j4 * 4 + 0] = v4.x; s[j4 * 4 + 1] = v4.y;
            s[j4 * 4 + 2] = v4.z; s[j4 * 4 + 3] = v4.w;
        }
        float mx = s[0];
        #pragma unroll
        for (int j = 1; j < 16; j++) mx = fmaxf(mx, s[j]);
        mx = fmaxf(mx, __shfl_xor_sync(0xffffffffu, mx, 1));
        mx = fmaxf(mx, __shfl_xor_sync(0xffffffffu, mx, 2));
        float mnew = fmaxf(m, mx);
        float corr = __expf(m - mnew);
        float rs = 0.f;
        #pragma unroll
        for (int j = 0; j < 16; j++) {
            float p = __expf(s[j] - mnew);
            rs += p;
            float phi = tf32_rna(p);
            Ph[myrow * AP + myg * 16 + j] = phi;
            Pl[myrow * AP + myg * 16 + j] = tf32_rna(p - phi);
        }
        rs += __shfl_xor_sync(0xffffffffu, rs, 1);
        rs += __shfl_xor_sync(0xffffffffu, rs, 2);
        m = mnew;
        l = l * corr + rs;
        if (myg == 0) cr[myrow] = corr;
        __syncthreads();

        // Rescale O frags
        float c0 = cr[wm + lr], c1 = cr[wm + lr + 8];
        #pragma unroll
        for (int nj = 0; nj < 5; nj++) {
            co[nj][0] *= c0; co[nj][1] *= c0;
            co[nj][2] *= c1; co[nj][3] *= c1;
        }

        // P@V: 3 compensated passes
        #pragma unroll
        for (int pass = 0; pass < 3; pass++) {
            const float* Av = (pass == 1) ? Pl : Ph;
            const float* Bv = (pass == 2) ? Vlo : Vhi;
            #pragma unroll
            for (int ks = 0; ks < 8; ks++) {
                int kc = ks * 8 + lc;
                unsigned a[4];
                a[0] = __float_as_uint(Av[(wm + lr) * AP + kc]);
                a[1] = __float_as_uint(Av[(wm + lr + 8) * AP + kc]);
                a[2] = __float_as_uint(Av[(wm + lr) * AP + kc + 4]);
                a[3] = __float_as_uint(Av[(wm + lr + 8) * AP + kc + 4]);
                #pragma unroll
                for (int nj = 0; nj < 5; nj++) {
                    int cn = wnp + nj * 8 + lr;
                    unsigned bb[2];
                    bb[0] = __float_as_uint(Bv[(kc)     * AV + cn]);
                    bb[1] = __float_as_uint(Bv[(kc + 4) * AV + cn]);
                    mma_tf32(co[nj], a, bb);
                }
            }
        }
    }

    // Epilogue
    __syncthreads();                 // all rescale-reads of cr done
    if (myg == 0) cr[myrow] = 1.f / l;
    __syncthreads();
    float i0 = cr[wm + lr], i1 = cr[wm + lr + 8];
    size_t ro0 = ((size_t)(b * S_ + q0 + wm + lr)) * (H_ * D_) + h * D_;
    size_t ro1 = ((size_t)(b * S_ + q0 + wm + lr + 8)) * (H_ * D_) + h * D_;
    #pragma unroll
    for (int nj = 0; nj < 5; nj++) {
        int col = wnp + nj * 8 + 2 * lc;
        *(float2*)(O + ro0 + col) =
            make_float2(tf32_rna(co[nj][0] * i0), tf32_rna(co[nj][1] * i0));
        *(float2*)(O + ro1 + col) =
            make_float2(tf32_rna(co[nj][2] * i1), tf32_rna(co[nj][3] * i1));
    }
}

// ---------------------------------------------------------------------------
// Launch
// ---------------------------------------------------------------------------
extern "C" void kernel_launch(void* const* d_in, const int* in_sizes, int n_in,
                              void* d_out, int out_size)
{
    const float* hs   = (const float*)d_in[0];
    const float* cosf = (const float*)d_in[1];
    const float* sinf = (const float*)d_in[2];
    const float* Wq   = (const float*)d_in[3];
    const float* Wk   = (const float*)d_in[4];
    const float* Wv   = (const float*)d_in[5];
    const float* Wo   = (const float*)d_in[6];
    float* out = (float*)d_out;

    float *Qp, *Kp, *Vp, *Cp, *HSr, *Wqr, *Wkr, *Wvr, *Wor;
    cudaGetSymbolAddress((void**)&Qp,  g_Q);
    cudaGetSymbolAddress((void**)&Kp,  g_K);
    cudaGetSymbolAddress((void**)&Vp,  g_V);
    cudaGetSymbolAddress((void**)&Cp,  g_ctx);
    cudaGetSymbolAddress((void**)&HSr, g_hs_r);
    cudaGetSymbolAddress((void**)&Wqr, g_Wq_r);
    cudaGetSymbolAddress((void**)&Wkr, g_Wk_r);
    cudaGetSymbolAddress((void**)&Wvr, g_Wv_r);
    cudaGetSymbolAddress((void**)&Wor, g_Wo_r);

    // TF32 RNA pre-rounding
    {
        auto rnd = [](const float* src, float* dst, size_t n) {
            int n4 = (int)(n / 4);
            round_tf32<<<(n4 + 255) / 256, 256>>>(
                (const float4*)src, (float4*)dst, n4);
        };
        rnd(hs, HSr, (size_t)BS_ * HID_);
        rnd(Wq, Wqr, (size_t)HID_ * H_ * D_);
        rnd(Wk, Wkr, (size_t)HID_ * KV_ * D_);
        rnd(Wv, Wvr, (size_t)HID_ * KV_ * D_);
        rnd(Wo, Wor, (size_t)H_ * D_ * HID_);
    }

    // Fused QKV projection
    {
        dim3 g(30, BS_ / 128);
        gemm_qkv<<<g, 256>>>(HSr, Wqr, Qp, Wkr, Kp, Wvr, Vp);
    }

    // RoPE on Q and K
    {
        size_t tq = (size_t)BS_ * H_ * 40;
        size_t tk = (size_t)BS_ * KV_ * 40;
        rope_kernel<<<(unsigned)((tq + 255) / 256), 256>>>(Qp, cosf, sinf, H_, tq);
        rope_kernel<<<(unsigned)((tk + 255) / 256), 256>>>(Kp, cosf, sinf, KV_, tk);
    }

    // Attention (tensor-core, 3xTF32)
    {
        const int smem = (4 * 64 * AQ + 2 * 64 * AV + 2 * 64 * AP + 64)
                         * (int)sizeof(float);   // 166,144 B
        cudaFuncSetAttribute(attn_mma,
                             cudaFuncAttributeMaxDynamicSharedMemorySize, smem);
        dim3 ga(S_ / 64, B_ * H_);
        attn_mma<<<ga, 256, smem>>>(Qp, Kp, Vp, Cp);
    }

    // Output projection
    {
        dim3 go(HID_ / 128, BS_ / 128);
        gemm_tf32<<<go, 256>>>(Cp, Wor, out, HID_, HID_);
    }
}